// round 7
// baseline (speedup 1.0000x reference)
#include <cuda_runtime.h>
#include <math.h>
#include <cstdint>

#define H 1024
#define NEXP 16
#define TOPK 6
#define EPS 1e-10f
#define MAXT 8192
#define SEG 8192

// GEMM tiling: 128x256x32 CTA tile, 512 threads, warp tile 32x64
#define BM 128
#define BN 256
#define BKK 32
#define NKT (H / BKK)          // 32
#define STG 3
#define RS 36                  // smem row stride in words (32 data + 4 pad)
#define A_BYTES (BM * RS * 4)           // 18432
#define B_BYTES (BN * RS * 4)           // 36864
#define STAGE_BYTES (A_BYTES + B_BYTES) // 55296
#define SM_TOK (STG * STAGE_BYTES)      // 165888
#define SM_W   (SM_TOK + 512)
#define SM_TOTAL (SM_W + 512)           // 166912

// ---------------- device scratch ----------------
__device__ int   g_cursor[NEXP];
__device__ float g_sw[MAXT];
__device__ int   g_pair_token[NEXP * SEG];
__device__ float g_pairw[NEXP * SEG];
__device__ int   g_pos[MAXT * TOPK];
__device__ float g_Yp[(size_t)NEXP * SEG * H];    // expert outputs
__device__ float g_Wt[(size_t)NEXP * H * H];      // W transposed [e][n][k], tf32, k-permuted
__device__ float g_Xt[(size_t)MAXT * H];          // X tf32, k-permuted

// k-permutation within each 8-group: logical p -> (p&3)*2 + (p>>2)
// so thread tg's LDS.64 pair (2tg, 2tg+1) = logical (tg, tg+4)
__device__ __forceinline__ int kperm(int k) {
    return (k & ~7) | (((k & 3) << 1) | ((k >> 2) & 1));
}

// ---------------- helpers ----------------
__device__ __forceinline__ unsigned f2tf(float f) {
    unsigned u;
    asm("cvt.rna.tf32.f32 %0, %1;" : "=r"(u) : "f"(f));
    return u;
}
__device__ __forceinline__ uint32_t s2u(const void* p) {
    uint32_t a;
    asm("{ .reg .u64 t; cvta.to.shared.u64 t, %1; cvt.u32.u64 %0, t; }"
        : "=r"(a) : "l"(p));
    return a;
}
__device__ __forceinline__ void cpa16(uint32_t dst, const void* src) {
    asm volatile("cp.async.cg.shared.global [%0], [%1], 16;" :: "r"(dst), "l"(src));
}
__device__ __forceinline__ void cpa_commit() {
    asm volatile("cp.async.commit_group;" ::: "memory");
}
__device__ __forceinline__ void cpa_wait1() {
    asm volatile("cp.async.wait_group 1;" ::: "memory");
}
__device__ __forceinline__ void lds64(unsigned& x, unsigned& y, uint32_t a) {
    asm volatile("ld.shared.v2.u32 {%0,%1}, [%2];" : "=r"(x), "=r"(y) : "r"(a));
}
__device__ __forceinline__ void mma8(float* c, const unsigned* a, const unsigned* b) {
    asm volatile(
        "mma.sync.aligned.m16n8k8.row.col.f32.tf32.tf32.f32 "
        "{%0,%1,%2,%3}, {%4,%5,%6,%7}, {%8,%9}, {%0,%1,%2,%3};"
        : "+f"(c[0]), "+f"(c[1]), "+f"(c[2]), "+f"(c[3])
        : "r"(a[0]), "r"(a[1]), "r"(a[2]), "r"(a[3]), "r"(b[0]), "r"(b[1]));
}

// ---------------- reset ----------------
__global__ void reset_kernel() {
    int i = threadIdx.x;
    if (i < NEXP) g_cursor[i] = 0;
}

// ---------------- transpose+cvt W: g_Wt[e][n][kperm(k)] = tf32(W[e][k][n]) ----------------
__global__ void transpose_kernel(const float* __restrict__ W) {
    __shared__ float t[32][33];
    int e = blockIdx.z;
    const float* w = W + (size_t)e * H * H;
    float* wt = g_Wt + (size_t)e * H * H;
    int tx = threadIdx.x, ty = threadIdx.y;
    int bx = blockIdx.x, by = blockIdx.y;
    #pragma unroll
    for (int j = 0; j < 4; ++j) {
        int y = by * 32 + ty + j * 8;
        t[ty + j * 8][tx] = w[(size_t)y * H + bx * 32 + tx];
    }
    __syncthreads();
    int k = by * 32 + tx;
    int kp = kperm(k);
    #pragma unroll
    for (int j = 0; j < 4; ++j) {
        int n = bx * 32 + ty + j * 8;
        wt[(size_t)n * H + kp] = __uint_as_float(f2tf(t[tx][ty + j * 8]));
    }
}

// ---------------- router: warp per token; converts X (k-permuted) and scatters ----------------
__global__ void router_kernel(const float* __restrict__ x,
                              const float* __restrict__ rw,
                              const float* __restrict__ rb, int T) {
    extern __shared__ float s_rw[];

    int tid = threadIdx.x;
    for (int i = tid; i < NEXP * H; i += blockDim.x) s_rw[i] = rw[i];
    __syncthreads();

    int warp = tid >> 5, lane = tid & 31;
    int t = blockIdx.x * (blockDim.x >> 5) + warp;
    if (t >= T) return;

    const float* xr = x + (size_t)t * H;
    float* xo = g_Xt + (size_t)t * H;
    float acc[NEXP];
    #pragma unroll
    for (int e = 0; e < NEXP; ++e) acc[e] = 0.f;
    for (int i = lane; i < H; i += 32) {
        float xv = xr[i];
        xo[kperm(i)] = __uint_as_float(f2tf(xv));
        #pragma unroll
        for (int e = 0; e < NEXP; ++e) acc[e] += xv * s_rw[e * H + i];
    }
    #pragma unroll
    for (int e = 0; e < NEXP; ++e) {
        #pragma unroll
        for (int o = 16; o > 0; o >>= 1)
            acc[e] += __shfl_xor_sync(0xffffffffu, acc[e], o);
    }
    float logit = (lane < NEXP) ? (acc[lane] + rb[lane]) : -INFINITY;

    float mx = logit;
    #pragma unroll
    for (int o = 16; o > 0; o >>= 1)
        mx = fmaxf(mx, __shfl_xor_sync(0xffffffffu, mx, o));
    float p = (lane < NEXP) ? expf(logit - mx) : 0.f;
    float sum = p;
    #pragma unroll
    for (int o = 16; o > 0; o >>= 1)
        sum += __shfl_xor_sync(0xffffffffu, sum, o);
    float prob = p / sum;

    float cur = (lane < NEXP) ? prob : -1.f;
    float tv[TOPK]; int ti[TOPK];
    float s = 0.f;
    #pragma unroll
    for (int k = 0; k < TOPK; ++k) {
        float v = cur; int bi = lane;
        #pragma unroll
        for (int o = 16; o > 0; o >>= 1) {
            float ov = __shfl_xor_sync(0xffffffffu, v, o);
            int   oi = __shfl_xor_sync(0xffffffffu, bi, o);
            if (ov > v || (ov == v && oi < bi)) { v = ov; bi = oi; }
        }
        tv[k] = v; ti[k] = bi;
        s += v;
        if (lane == bi) cur = -1.f;
    }
    if (lane == 0) {
        float inv = 1.f / (s + EPS);
        float w[TOPK], sw = 0.f;
        #pragma unroll
        for (int k = 0; k < TOPK; ++k) { w[k] = tv[k] * inv; sw += w[k]; }
        g_sw[t] = sw;
        float isw = 1.f / sw;
        int b = t * TOPK;
        #pragma unroll
        for (int k = 0; k < TOPK; ++k) {
            int e = ti[k];
            int pos = atomicAdd(&g_cursor[e], 1);
            int row = e * SEG + pos;
            g_pair_token[row] = t;
            g_pairw[row] = w[k] * isw;
            g_pos[b + k] = row;
        }
    }
}

// ---------------- grouped GEMM: 512 thr, warp tile 32x64, LDS.64 frags ----------------
__global__ void __launch_bounds__(512, 1) gemm_kernel() {
    extern __shared__ char smem[];
    const int e   = blockIdx.z;
    const int cnt = g_cursor[e];
    const int mb  = blockIdx.y * BM;
    if (mb >= cnt) return;
    const int base = e * SEG + mb;
    const int n0 = blockIdx.x * BN;

    const uint32_t sb = s2u(smem);
    const int tid = threadIdx.x;
    int*   s_tok = (int*)(smem + SM_TOK);
    float* s_w   = (float*)(smem + SM_W);

    if (tid < BM) {
        bool ok = (mb + tid) < cnt;
        s_tok[tid] = ok ? g_pair_token[base + tid] : 0;
        s_w[tid]   = ok ? g_pairw[base + tid] : 0.f;
    }
    __syncthreads();

    const float* wb = g_Wt + (size_t)e * H * H + (size_t)n0 * H;

    // A: 1024 16B-chunks (2/thread); B: 2048 chunks (4/thread). Rows are 128B of k.
    auto issue = [&](int s, int kt) {
        const int k0 = kt * BKK;
        uint32_t ab = sb + s * STAGE_BYTES;
        #pragma unroll
        for (int p = 0; p < 2; ++p) {
            int idx = tid + p * 512;
            int row = idx >> 3, i = idx & 7;
            cpa16(ab + (row * RS + i * 4) * 4,
                  g_Xt + (size_t)s_tok[row] * H + k0 + i * 4);
        }
        uint32_t bb = ab + A_BYTES;
        #pragma unroll
        for (int p = 0; p < 4; ++p) {
            int idx = tid + p * 512;
            int row = idx >> 3, i = idx & 7;
            cpa16(bb + (row * RS + i * 4) * 4,
                  wb + (size_t)row * H + k0 + i * 4);
        }
    };

    issue(0, 0); cpa_commit();
    issue(1, 1); cpa_commit();

    float c[2][8][4];
    #pragma unroll
    for (int mi = 0; mi < 2; ++mi)
        #pragma unroll
        for (int ni = 0; ni < 8; ++ni)
            #pragma unroll
            for (int j = 0; j < 4; ++j) c[mi][ni][j] = 0.f;

    const int lane = tid & 31;
    const int grp = lane >> 2, tg = lane & 3;
    const int wid = tid >> 5;
    const int wm = (wid & 3) * 32;     // 4 warp rows of 32
    const int wn = (wid >> 2) * 64;    // 4 warp cols of 64

    for (int kt = 0; kt < NKT; ++kt) {
        cpa_wait1();
        __syncthreads();
        if (kt + 2 < NKT) issue((kt + 2) % STG, kt + 2);
        cpa_commit();   // commit every iteration keeps wait_group(1) sound at tail

        const uint32_t abase = sb + (kt % STG) * STAGE_BYTES;
        const uint32_t bbase = abase + A_BYTES;

        #pragma unroll
        for (int kk = 0; kk < 4; ++kk) {
            const uint32_t koff = (kk * 8 + tg * 2) * 4;
            unsigned a[2][4], b[8][2];
            #pragma unroll
            for (int mi = 0; mi < 2; ++mi) {
                int r = wm + mi * 16 + grp;
                lds64(a[mi][0], a[mi][2], abase + (uint32_t)(r * RS) * 4 + koff);
                lds64(a[mi][1], a[mi][3], abase + (uint32_t)((r + 8) * RS) * 4 + koff);
            }
            #pragma unroll
            for (int ni = 0; ni < 8; ++ni) {
                int cn = wn + ni * 8 + grp;
                lds64(b[ni][0], b[ni][1], bbase + (uint32_t)(cn * RS) * 4 + koff);
            }
            #pragma unroll
            for (int mi = 0; mi < 2; ++mi)
                #pragma unroll
                for (int ni = 0; ni < 8; ++ni)
                    mma8(c[mi][ni], a[mi], b[ni]);
        }
    }

    // epilogue: scale by pair weight, store float2
    #pragma unroll
    for (int mi = 0; mi < 2; ++mi) {
        int rl0 = wm + mi * 16 + grp;
        int rl1 = rl0 + 8;
        float w0 = s_w[rl0], w1 = s_w[rl1];
        #pragma unroll
        for (int ni = 0; ni < 8; ++ni) {
            int col = n0 + wn + ni * 8 + tg * 2;
            if (mb + rl0 < cnt) {
                float2 v = make_float2(c[mi][ni][0] * w0, c[mi][ni][1] * w0);
                *(float2*)&g_Yp[(size_t)(base + rl0) * H + col] = v;
            }
            if (mb + rl1 < cnt) {
                float2 v = make_float2(c[mi][ni][2] * w1, c[mi][ni][3] * w1);
                *(float2*)&g_Yp[(size_t)(base + rl1) * H + col] = v;
            }
        }
    }
}

// ---------------- combine: out[t] = EPS*sw + sum_k Yp[pos_k] ----------------
__global__ void combine_kernel(float* __restrict__ out, int T) {
    int t = blockIdx.x;
    int c4 = threadIdx.x;
    int b = t * TOPK;
    int p0 = g_pos[b + 0], p1 = g_pos[b + 1], p2 = g_pos[b + 2];
    int p3 = g_pos[b + 3], p4 = g_pos[b + 4], p5 = g_pos[b + 5];
    float bias = EPS * g_sw[t];
    int col = c4 * 4;

    float4 acc = make_float4(bias, bias, bias, bias);
    float4 y;
    y = *(const float4*)&g_Yp[(size_t)p0 * H + col]; acc.x += y.x; acc.y += y.y; acc.z += y.z; acc.w += y.w;
    y = *(const float4*)&g_Yp[(size_t)p1 * H + col]; acc.x += y.x; acc.y += y.y; acc.z += y.z; acc.w += y.w;
    y = *(const float4*)&g_Yp[(size_t)p2 * H + col]; acc.x += y.x; acc.y += y.y; acc.z += y.z; acc.w += y.w;
    y = *(const float4*)&g_Yp[(size_t)p3 * H + col]; acc.x += y.x; acc.y += y.y; acc.z += y.z; acc.w += y.w;
    y = *(const float4*)&g_Yp[(size_t)p4 * H + col]; acc.x += y.x; acc.y += y.y; acc.z += y.z; acc.w += y.w;
    y = *(const float4*)&g_Yp[(size_t)p5 * H + col]; acc.x += y.x; acc.y += y.y; acc.z += y.z; acc.w += y.w;

    *(float4*)&out[(size_t)t * H + col] = acc;
}

// ---------------- launch ----------------
extern "C" void kernel_launch(void* const* d_in, const int* in_sizes, int n_in,
                              void* d_out, int out_size) {
    const float* tokens = (const float*)d_in[0];
    const float* rw     = (const float*)d_in[1];
    const float* rb     = (const float*)d_in[2];
    const float* ew     = (const float*)d_in[3];
    float* out = (float*)d_out;

    int T = in_sizes[0] / H;   // 8192

    reset_kernel<<<1, 32>>>();                                        // idx 0

    transpose_kernel<<<dim3(32, 32, NEXP), dim3(32, 8)>>>(ew);        // idx 1

    cudaFuncSetAttribute(router_kernel,
                         cudaFuncAttributeMaxDynamicSharedMemorySize, NEXP * H * 4);
    int warps_per_blk = 8;
    int rblocks = (T + warps_per_blk - 1) / warps_per_blk;
    router_kernel<<<rblocks, warps_per_blk * 32, NEXP * H * 4>>>(tokens, rw, rb, T);  // idx 2

    cudaFuncSetAttribute(gemm_kernel,
                         cudaFuncAttributeMaxDynamicSharedMemorySize, SM_TOTAL);
    dim3 ggrid(H / BN, SEG / BM, NEXP);   // (4, 64, 16)
    gemm_kernel<<<ggrid, 512, SM_TOTAL>>>();                          // idx 3 <- profiled

    combine_kernel<<<T, 256>>>(out, T);                               // idx 4
}

// round 8
// speedup vs baseline: 1.3196x; 1.3196x over previous
#include <cuda_runtime.h>
#include <math.h>
#include <cstdint>

#define H 1024
#define NEXP 16
#define TOPK 6
#define EPS 1e-10f
#define MAXT 8192
#define SEG 8192

// GEMM tiling: 128x256x64 CTA tile, 256 threads, warp tile 64x64 (round-6 layout)
#define BM 128
#define BN 256
#define BKK 64
#define NKT (H / BKK)          // 16
#define STG 2
#define AST 68                 // A smem row stride words (64 data + 4 pad)
#define BSTRIDE 264            // B smem row stride words (256 data + 8 pad)
#define A_BYTES (BM * AST * 4)           // 34816
#define B_BYTES (BKK * BSTRIDE * 4)      // 67584
#define STAGE_BYTES (A_BYTES + B_BYTES)  // 102400
#define SM_TOK (STG * STAGE_BYTES)       // 204800
#define SM_W   (SM_TOK + 512)
#define SM_TOTAL (SM_W + 512)            // 205824

// ---------------- device scratch ----------------
__device__ int   g_cursor[NEXP];
__device__ float g_sw[MAXT];
__device__ int   g_pair_token[NEXP * SEG];
__device__ float g_pairw[NEXP * SEG];
__device__ int   g_pos[MAXT * TOPK];
__device__ float g_Yp[(size_t)NEXP * SEG * H];    // expert outputs
__device__ float g_Wt[(size_t)NEXP * H * H];      // W tf32-converted, original [k][n]
__device__ float g_Xt[(size_t)MAXT * H];          // X tf32-converted

// ---------------- helpers ----------------
__device__ __forceinline__ unsigned f2tf(float f) {
    unsigned u;
    asm("cvt.rna.tf32.f32 %0, %1;" : "=r"(u) : "f"(f));
    return u;
}
__device__ __forceinline__ uint32_t s2u(const void* p) {
    uint32_t a;
    asm("{ .reg .u64 t; cvta.to.shared.u64 t, %1; cvt.u32.u64 %0, t; }"
        : "=r"(a) : "l"(p));
    return a;
}
__device__ __forceinline__ void cpa16(uint32_t dst, const void* src) {
    asm volatile("cp.async.cg.shared.global [%0], [%1], 16;" :: "r"(dst), "l"(src));
}
__device__ __forceinline__ void cpa_commit() {
    asm volatile("cp.async.commit_group;" ::: "memory");
}
__device__ __forceinline__ void cpa_wait1() {
    asm volatile("cp.async.wait_group 1;" ::: "memory");
}
__device__ __forceinline__ void mma8(float* c, const unsigned* a, const unsigned* b) {
    asm volatile(
        "mma.sync.aligned.m16n8k8.row.col.f32.tf32.tf32.f32 "
        "{%0,%1,%2,%3}, {%4,%5,%6,%7}, {%8,%9}, {%0,%1,%2,%3};"
        : "+f"(c[0]), "+f"(c[1]), "+f"(c[2]), "+f"(c[3])
        : "r"(a[0]), "r"(a[1]), "r"(a[2]), "r"(a[3]), "r"(b[0]), "r"(b[1]));
}

// ---------------- reset ----------------
__global__ void reset_kernel() {
    int i = threadIdx.x;
    if (i < NEXP) g_cursor[i] = 0;
}

// ---------------- cvt W -> tf32 bit patterns (layout unchanged) ----------------
__global__ void cvt_w_kernel(const float* __restrict__ src, int n4) {
    int i = blockIdx.x * blockDim.x + threadIdx.x;
    if (i >= n4) return;
    float4 v = ((const float4*)src)[i];
    uint4 u;
    u.x = f2tf(v.x); u.y = f2tf(v.y); u.z = f2tf(v.z); u.w = f2tf(v.w);
    ((uint4*)g_Wt)[i] = u;
}

// ---------------- router: warp per token; converts X and scatters ----------------
__global__ void router_kernel(const float* __restrict__ x,
                              const float* __restrict__ rw,
                              const float* __restrict__ rb, int T) {
    extern __shared__ float s_rw[];

    int tid = threadIdx.x;
    for (int i = tid; i < NEXP * H; i += blockDim.x) s_rw[i] = rw[i];
    __syncthreads();

    int warp = tid >> 5, lane = tid & 31;
    int t = blockIdx.x * (blockDim.x >> 5) + warp;
    if (t >= T) return;

    const float* xr = x + (size_t)t * H;
    float* xo = g_Xt + (size_t)t * H;
    float acc[NEXP];
    #pragma unroll
    for (int e = 0; e < NEXP; ++e) acc[e] = 0.f;
    for (int i = lane; i < H; i += 32) {
        float xv = xr[i];
        xo[i] = __uint_as_float(f2tf(xv));
        #pragma unroll
        for (int e = 0; e < NEXP; ++e) acc[e] += xv * s_rw[e * H + i];
    }
    #pragma unroll
    for (int e = 0; e < NEXP; ++e) {
        #pragma unroll
        for (int o = 16; o > 0; o >>= 1)
            acc[e] += __shfl_xor_sync(0xffffffffu, acc[e], o);
    }
    float logit = (lane < NEXP) ? (acc[lane] + rb[lane]) : -INFINITY;

    float mx = logit;
    #pragma unroll
    for (int o = 16; o > 0; o >>= 1)
        mx = fmaxf(mx, __shfl_xor_sync(0xffffffffu, mx, o));
    float p = (lane < NEXP) ? expf(logit - mx) : 0.f;
    float sum = p;
    #pragma unroll
    for (int o = 16; o > 0; o >>= 1)
        sum += __shfl_xor_sync(0xffffffffu, sum, o);
    float prob = p / sum;

    float cur = (lane < NEXP) ? prob : -1.f;
    float tv[TOPK]; int ti[TOPK];
    float s = 0.f;
    #pragma unroll
    for (int k = 0; k < TOPK; ++k) {
        float v = cur; int bi = lane;
        #pragma unroll
        for (int o = 16; o > 0; o >>= 1) {
            float ov = __shfl_xor_sync(0xffffffffu, v, o);
            int   oi = __shfl_xor_sync(0xffffffffu, bi, o);
            if (ov > v || (ov == v && oi < bi)) { v = ov; bi = oi; }
        }
        tv[k] = v; ti[k] = bi;
        s += v;
        if (lane == bi) cur = -1.f;
    }
    if (lane == 0) {
        float inv = 1.f / (s + EPS);
        float w[TOPK], sw = 0.f;
        #pragma unroll
        for (int k = 0; k < TOPK; ++k) { w[k] = tv[k] * inv; sw += w[k]; }
        g_sw[t] = sw;
        float isw = 1.f / sw;
        int b = t * TOPK;
        #pragma unroll
        for (int k = 0; k < TOPK; ++k) {
            int e = ti[k];
            int pos = atomicAdd(&g_cursor[e], 1);
            int row = e * SEG + pos;
            g_pair_token[row] = t;
            g_pairw[row] = w[k] * isw;
            g_pos[b + k] = row;
        }
    }
}

// ---------------- grouped GEMM: 128x256x64, 2-stage, frag double-buffer ----------------
__global__ void __launch_bounds__(256) gemm_kernel() {
    extern __shared__ char smem[];
    const int e   = blockIdx.z;
    const int cnt = g_cursor[e];
    const int mb  = blockIdx.y * BM;
    if (mb >= cnt) return;
    const int base = e * SEG + mb;
    const int n0 = blockIdx.x * BN;

    const uint32_t sb = s2u(smem);
    const int tid = threadIdx.x;
    int*   s_tok = (int*)(smem + SM_TOK);
    float* s_w   = (float*)(smem + SM_W);

    if (tid < BM) {
        bool ok = (mb + tid) < cnt;
        s_tok[tid] = ok ? g_pair_token[base + tid] : 0;
        s_w[tid]   = ok ? g_pairw[base + tid] : 0.f;
    }
    __syncthreads();

    const float* wb = g_Wt + (size_t)e * H * H + n0;

    // stage issue: A = 8 x cp16 / thread (128 rows x 16 chunks), B = 16 x cp16 (64 rows x 64 chunks)
    auto issue = [&](int s, int kt) {
        const int k0 = kt * BKK;
        uint32_t ab = sb + s * STAGE_BYTES;
        #pragma unroll
        for (int p = 0; p < 8; ++p) {
            int idx = tid + p * 256;
            int row = idx >> 4, i = idx & 15;
            cpa16(ab + (row * AST + i * 4) * 4,
                  g_Xt + (size_t)s_tok[row] * H + k0 + i * 4);
        }
        uint32_t bb = ab + A_BYTES;
        #pragma unroll
        for (int p = 0; p < 16; ++p) {
            int idx = tid + p * 256;
            int kr = idx >> 6, i = idx & 63;
            cpa16(bb + (kr * BSTRIDE + i * 4) * 4,
                  wb + (size_t)(k0 + kr) * H + i * 4);
        }
    };

    issue(0, 0); cpa_commit();
    issue(1, 1); cpa_commit();

    float c[4][8][4];
    #pragma unroll
    for (int mi = 0; mi < 4; ++mi)
        #pragma unroll
        for (int ni = 0; ni < 8; ++ni)
            #pragma unroll
            for (int j = 0; j < 4; ++j) c[mi][ni][j] = 0.f;

    const int lane = tid & 31;
    const int grp = lane >> 2, tg = lane & 3;
    const int wid = tid >> 5;
    const int wm = (wid >> 2) * 64;   // 2 warp rows
    const int wn = (wid & 3) * 64;    // 4 warp cols

    unsigned a[2][4][4], b[2][8][2];

    #define LOADF(buf, kk)                                                   \
        { const int k8 = (kk) * 8;                                           \
          _Pragma("unroll")                                                  \
          for (int mi = 0; mi < 4; ++mi) {                                   \
            int r = wm + mi * 16 + grp;                                      \
            a[buf][mi][0] = As[r * AST + k8 + tg];                           \
            a[buf][mi][1] = As[(r + 8) * AST + k8 + tg];                     \
            a[buf][mi][2] = As[r * AST + k8 + tg + 4];                       \
            a[buf][mi][3] = As[(r + 8) * AST + k8 + tg + 4];                 \
          }                                                                  \
          _Pragma("unroll")                                                  \
          for (int ni = 0; ni < 8; ++ni) {                                   \
            int cn = wn + ni * 8 + grp;                                      \
            b[buf][ni][0] = Bs[(k8 + tg) * BSTRIDE + cn];                    \
            b[buf][ni][1] = Bs[(k8 + tg + 4) * BSTRIDE + cn];                \
          } }

    for (int kt = 0; kt < NKT; ++kt) {
        cpa_wait1();
        __syncthreads();

        const unsigned* As = (const unsigned*)(smem + (kt & 1) * STAGE_BYTES);
        const unsigned* Bs = As + BM * AST;

        LOADF(0, 0);
        #pragma unroll
        for (int kk = 0; kk < 8; ++kk) {
            const int cur = kk & 1;
            if (kk < 7) LOADF(cur ^ 1, kk + 1);   // prefetch next frags during MMA
            #pragma unroll
            for (int mi = 0; mi < 4; ++mi)
                #pragma unroll
                for (int ni = 0; ni < 8; ++ni)
                    mma8(c[mi][ni], a[cur][mi], b[cur][ni]);
        }

        __syncthreads();   // all warps done reading this stage
        if (kt + 2 < NKT) issue(kt & 1, kt + 2);
        cpa_commit();      // commit every iteration keeps wait_group(1) sound
    }
    #undef LOADF

    // epilogue: scale by pair weight, store float2
    #pragma unroll
    for (int mi = 0; mi < 4; ++mi) {
        int rl0 = wm + mi * 16 + grp;
        int rl1 = rl0 + 8;
        float w0 = s_w[rl0], w1 = s_w[rl1];
        #pragma unroll
        for (int ni = 0; ni < 8; ++ni) {
            int col = n0 + wn + ni * 8 + tg * 2;
            if (mb + rl0 < cnt) {
                float2 v = make_float2(c[mi][ni][0] * w0, c[mi][ni][1] * w0);
                *(float2*)&g_Yp[(size_t)(base + rl0) * H + col] = v;
            }
            if (mb + rl1 < cnt) {
                float2 v = make_float2(c[mi][ni][2] * w1, c[mi][ni][3] * w1);
                *(float2*)&g_Yp[(size_t)(base + rl1) * H + col] = v;
            }
        }
    }
}

// ---------------- combine: out[t] = EPS*sw + sum_k Yp[pos_k] ----------------
__global__ void combine_kernel(float* __restrict__ out, int T) {
    int t = blockIdx.x;
    int c4 = threadIdx.x;
    int b = t * TOPK;
    int p0 = g_pos[b + 0], p1 = g_pos[b + 1], p2 = g_pos[b + 2];
    int p3 = g_pos[b + 3], p4 = g_pos[b + 4], p5 = g_pos[b + 5];
    float bias = EPS * g_sw[t];
    int col = c4 * 4;

    float4 acc = make_float4(bias, bias, bias, bias);
    float4 y;
    y = *(const float4*)&g_Yp[(size_t)p0 * H + col]; acc.x += y.x; acc.y += y.y; acc.z += y.z; acc.w += y.w;
    y = *(const float4*)&g_Yp[(size_t)p1 * H + col]; acc.x += y.x; acc.y += y.y; acc.z += y.z; acc.w += y.w;
    y = *(const float4*)&g_Yp[(size_t)p2 * H + col]; acc.x += y.x; acc.y += y.y; acc.z += y.z; acc.w += y.w;
    y = *(const float4*)&g_Yp[(size_t)p3 * H + col]; acc.x += y.x; acc.y += y.y; acc.z += y.z; acc.w += y.w;
    y = *(const float4*)&g_Yp[(size_t)p4 * H + col]; acc.x += y.x; acc.y += y.y; acc.z += y.z; acc.w += y.w;
    y = *(const float4*)&g_Yp[(size_t)p5 * H + col]; acc.x += y.x; acc.y += y.y; acc.z += y.z; acc.w += y.w;

    *(float4*)&out[(size_t)t * H + col] = acc;
}

// ---------------- launch ----------------
extern "C" void kernel_launch(void* const* d_in, const int* in_sizes, int n_in,
                              void* d_out, int out_size) {
    const float* tokens = (const float*)d_in[0];
    const float* rw     = (const float*)d_in[1];
    const float* rb     = (const float*)d_in[2];
    const float* ew     = (const float*)d_in[3];
    float* out = (float*)d_out;

    int T = in_sizes[0] / H;   // 8192

    reset_kernel<<<1, 32>>>();                                        // idx 0

    cvt_w_kernel<<<(NEXP * H * H / 4 + 255) / 256, 256>>>(ew, NEXP * H * H / 4);  // idx 1

    cudaFuncSetAttribute(router_kernel,
                         cudaFuncAttributeMaxDynamicSharedMemorySize, NEXP * H * 4);
    int warps_per_blk = 8;
    int rblocks = (T + warps_per_blk - 1) / warps_per_blk;
    router_kernel<<<rblocks, warps_per_blk * 32, NEXP * H * 4>>>(tokens, rw, rb, T);  // idx 2

    cudaFuncSetAttribute(gemm_kernel,
                         cudaFuncAttributeMaxDynamicSharedMemorySize, SM_TOTAL);
    dim3 ggrid(H / BN, SEG / BM, NEXP);   // (4, 64, 16)
    gemm_kernel<<<ggrid, 256, SM_TOTAL>>>();                          // idx 3 <- profiled

    combine_kernel<<<T, 256>>>(out, T);                               // idx 4
}

// round 9
// speedup vs baseline: 1.4301x; 1.0838x over previous
#include <cuda_runtime.h>
#include <math.h>
#include <cstdint>

#define H 1024
#define NEXP 16
#define TOPK 6
#define EPS 1e-10f
#define MAXT 8192
#define SEG 8192

// GEMM: CTA tile 128x128x32, 128 threads (4 warps, 2x2 grid of 64x64 warp tiles),
// 3 smem stages, 2 CTAs/SM.
#define BM 128
#define BN 128
#define BKK 32
#define NKT (H / BKK)          // 32
#define STG 3
#define AST 36                 // A row stride words (32 data + 4 pad)
#define BSTRIDE 136            // B row stride words (128 data + 8 pad)
#define A_BYTES (BM * AST * 4)           // 18432
#define B_BYTES (BKK * BSTRIDE * 4)      // 17408
#define STAGE_BYTES (A_BYTES + B_BYTES)  // 35840
#define SM_TOK (STG * STAGE_BYTES)       // 107520
#define SM_W   (SM_TOK + 512)
#define SM_TOTAL (SM_W + 512)            // 108544 (x2 CTAs = 217KB <= 227KB)

// ---------------- device scratch ----------------
__device__ int   g_cursor[NEXP];
__device__ float g_sw[MAXT];
__device__ int   g_pair_token[NEXP * SEG];
__device__ float g_pairw[NEXP * SEG];
__device__ int   g_pos[MAXT * TOPK];
__device__ float g_Yp[(size_t)NEXP * SEG * H];
__device__ float g_Wt[(size_t)NEXP * H * H];      // W tf32-converted
__device__ float g_Xt[(size_t)MAXT * H];          // X tf32-converted

// ---------------- helpers ----------------
__device__ __forceinline__ unsigned f2tf(float f) {
    unsigned u;
    asm("cvt.rna.tf32.f32 %0, %1;" : "=r"(u) : "f"(f));
    return u;
}
__device__ __forceinline__ uint32_t s2u(const void* p) {
    uint32_t a;
    asm("{ .reg .u64 t; cvta.to.shared.u64 t, %1; cvt.u32.u64 %0, t; }"
        : "=r"(a) : "l"(p));
    return a;
}
__device__ __forceinline__ void cpa16(uint32_t dst, const void* src) {
    asm volatile("cp.async.cg.shared.global [%0], [%1], 16;" :: "r"(dst), "l"(src));
}
__device__ __forceinline__ void cpa_commit() {
    asm volatile("cp.async.commit_group;" ::: "memory");
}
__device__ __forceinline__ void cpa_wait1() {
    asm volatile("cp.async.wait_group 1;" ::: "memory");
}
__device__ __forceinline__ void mma8(float* c, const unsigned* a, const unsigned* b) {
    asm volatile(
        "mma.sync.aligned.m16n8k8.row.col.f32.tf32.tf32.f32 "
        "{%0,%1,%2,%3}, {%4,%5,%6,%7}, {%8,%9}, {%0,%1,%2,%3};"
        : "+f"(c[0]), "+f"(c[1]), "+f"(c[2]), "+f"(c[3])
        : "r"(a[0]), "r"(a[1]), "r"(a[2]), "r"(a[3]), "r"(b[0]), "r"(b[1]));
}

// ---------------- reset ----------------
__global__ void reset_kernel() {
    int i = threadIdx.x;
    if (i < NEXP) g_cursor[i] = 0;
}

// ---------------- cvt W -> tf32 ----------------
__global__ void cvt_w_kernel(const float* __restrict__ src, int n4) {
    int i = blockIdx.x * blockDim.x + threadIdx.x;
    if (i >= n4) return;
    float4 v = ((const float4*)src)[i];
    uint4 u;
    u.x = f2tf(v.x); u.y = f2tf(v.y); u.z = f2tf(v.z); u.w = f2tf(v.w);
    ((uint4*)g_Wt)[i] = u;
}

// ---------------- router: 2 tokens per warp; converts X and scatters ----------------
__global__ void router_kernel(const float* __restrict__ x,
                              const float* __restrict__ rw,
                              const float* __restrict__ rb, int T) {
    extern __shared__ float s_rw[];

    int tid = threadIdx.x;
    for (int i = tid; i < NEXP * H; i += blockDim.x) s_rw[i] = rw[i];
    __syncthreads();

    int warp = tid >> 5, lane = tid & 31;
    int t0 = (blockIdx.x * (blockDim.x >> 5) + warp) * 2;
    if (t0 >= T) return;

    const float* xr0 = x + (size_t)t0 * H;
    const float* xr1 = x + (size_t)(t0 + 1) * H;
    float* xo0 = g_Xt + (size_t)t0 * H;
    float* xo1 = g_Xt + (size_t)(t0 + 1) * H;

    float acc0[NEXP], acc1[NEXP];
    #pragma unroll
    for (int e = 0; e < NEXP; ++e) { acc0[e] = 0.f; acc1[e] = 0.f; }
    for (int i = lane; i < H; i += 32) {
        float xv0 = xr0[i], xv1 = xr1[i];
        xo0[i] = __uint_as_float(f2tf(xv0));
        xo1[i] = __uint_as_float(f2tf(xv1));
        #pragma unroll
        for (int e = 0; e < NEXP; ++e) {
            float w = s_rw[e * H + i];
            acc0[e] += xv0 * w;
            acc1[e] += xv1 * w;
        }
    }

    #pragma unroll
    for (int tk = 0; tk < 2; ++tk) {
        int t = t0 + tk;
        float logit;
        {
            float a[NEXP];
            #pragma unroll
            for (int e = 0; e < NEXP; ++e) a[e] = tk ? acc1[e] : acc0[e];
            #pragma unroll
            for (int e = 0; e < NEXP; ++e) {
                #pragma unroll
                for (int o = 16; o > 0; o >>= 1)
                    a[e] += __shfl_xor_sync(0xffffffffu, a[e], o);
            }
            logit = (lane < NEXP) ? (a[lane] + rb[lane]) : -INFINITY;
        }

        float mx = logit;
        #pragma unroll
        for (int o = 16; o > 0; o >>= 1)
            mx = fmaxf(mx, __shfl_xor_sync(0xffffffffu, mx, o));
        float p = (lane < NEXP) ? expf(logit - mx) : 0.f;
        float sum = p;
        #pragma unroll
        for (int o = 16; o > 0; o >>= 1)
            sum += __shfl_xor_sync(0xffffffffu, sum, o);
        float prob = p / sum;

        float cur = (lane < NEXP) ? prob : -1.f;
        float tv[TOPK]; int ti[TOPK];
        float s = 0.f;
        #pragma unroll
        for (int k = 0; k < TOPK; ++k) {
            float v = cur; int bi = lane;
            #pragma unroll
            for (int o = 16; o > 0; o >>= 1) {
                float ov = __shfl_xor_sync(0xffffffffu, v, o);
                int   oi = __shfl_xor_sync(0xffffffffu, bi, o);
                if (ov > v || (ov == v && oi < bi)) { v = ov; bi = oi; }
            }
            tv[k] = v; ti[k] = bi;
            s += v;
            if (lane == bi) cur = -1.f;
        }
        if (lane == 0) {
            float inv = 1.f / (s + EPS);
            float w[TOPK], sw = 0.f;
            #pragma unroll
            for (int k = 0; k < TOPK; ++k) { w[k] = tv[k] * inv; sw += w[k]; }
            g_sw[t] = sw;
            float isw = 1.f / sw;
            int b = t * TOPK;
            #pragma unroll
            for (int k = 0; k < TOPK; ++k) {
                int e = ti[k];
                int pos = atomicAdd(&g_cursor[e], 1);
                int row = e * SEG + pos;
                g_pair_token[row] = t;
                g_pairw[row] = w[k] * isw;
                g_pos[b + k] = row;
            }
        }
    }
}

// ---------------- grouped GEMM: 128x128x32, 128 thr, 3-stage, 2 CTAs/SM ----------------
__global__ void __launch_bounds__(128, 2) gemm_kernel() {
    extern __shared__ char smem[];
    const int e   = blockIdx.z;
    const int cnt = g_cursor[e];
    const int mb  = blockIdx.y * BM;
    if (mb >= cnt) return;
    const int base = e * SEG + mb;
    const int n0 = blockIdx.x * BN;

    const uint32_t sb = s2u(smem);
    const int tid = threadIdx.x;
    int*   s_tok = (int*)(smem + SM_TOK);
    float* s_w   = (float*)(smem + SM_W);

    if (tid < BM) {
        bool ok = (mb + tid) < cnt;
        s_tok[tid] = ok ? g_pair_token[base + tid] : 0;
        s_w[tid]   = ok ? g_pairw[base + tid] : 0.f;
    }
    __syncthreads();

    const float* wb = g_Wt + (size_t)e * H * H + n0;

    // per stage: A 128x8 chunks, B 32x32 chunks; 8 cp16/thread each
    auto issue = [&](int s, int kt) {
        const int k0 = kt * BKK;
        uint32_t ab = sb + s * STAGE_BYTES;
        #pragma unroll
        for (int p = 0; p < 8; ++p) {
            int idx = tid + p * 128;
            int row = idx >> 3, i = idx & 7;
            cpa16(ab + (row * AST + i * 4) * 4,
                  g_Xt + (size_t)s_tok[row] * H + k0 + i * 4);
        }
        uint32_t bb = ab + A_BYTES;
        #pragma unroll
        for (int p = 0; p < 8; ++p) {
            int idx = tid + p * 128;
            int kr = idx >> 5, i = idx & 31;
            cpa16(bb + (kr * BSTRIDE + i * 4) * 4,
                  wb + (size_t)(k0 + kr) * H + i * 4);
        }
    };

    issue(0, 0); cpa_commit();
    issue(1, 1); cpa_commit();

    float c[4][8][4];
    #pragma unroll
    for (int mi = 0; mi < 4; ++mi)
        #pragma unroll
        for (int ni = 0; ni < 8; ++ni)
            #pragma unroll
            for (int j = 0; j < 4; ++j) c[mi][ni][j] = 0.f;

    const int lane = tid & 31;
    const int grp = lane >> 2, tg = lane & 3;
    const int wid = tid >> 5;
    const int wm = (wid >> 1) * 64;   // 2 warp rows
    const int wn = (wid & 1) * 64;    // 2 warp cols

    unsigned a[2][4][4], b[2][8][2];

    #define LOADF(buf, kk)                                                   \
        { const int k8 = (kk) * 8;                                           \
          _Pragma("unroll")                                                  \
          for (int mi = 0; mi < 4; ++mi) {                                   \
            int r = wm + mi * 16 + grp;                                      \
            a[buf][mi][0] = As[r * AST + k8 + tg];                           \
            a[buf][mi][1] = As[(r + 8) * AST + k8 + tg];                     \
            a[buf][mi][2] = As[r * AST + k8 + tg + 4];                       \
            a[buf][mi][3] = As[(r + 8) * AST + k8 + tg + 4];                 \
          }                                                                  \
          _Pragma("unroll")                                                  \
          for (int ni = 0; ni < 8; ++ni) {                                   \
            int cn = wn + ni * 8 + grp;                                      \
            b[buf][ni][0] = Bs[(k8 + tg) * BSTRIDE + cn];                    \
            b[buf][ni][1] = Bs[(k8 + tg + 4) * BSTRIDE + cn];                \
          } }

    for (int kt = 0; kt < NKT; ++kt) {
        cpa_wait1();
        __syncthreads();          // single barrier per k-tile (3 stages)
        if (kt + 2 < NKT) issue((kt + 2) % STG, kt + 2);
        cpa_commit();             // commit every iter keeps wait_group(1) sound

        const unsigned* As = (const unsigned*)(smem + (kt % STG) * STAGE_BYTES);
        const unsigned* Bs = As + BM * AST;

        LOADF(0, 0);
        #pragma unroll
        for (int kk = 0; kk < 4; ++kk) {
            const int cur = kk & 1;
            if (kk < 3) LOADF(cur ^ 1, kk + 1);
            #pragma unroll
            for (int mi = 0; mi < 4; ++mi)
                #pragma unroll
                for (int ni = 0; ni < 8; ++ni)
                    mma8(c[mi][ni], a[cur][mi], b[cur][ni]);
        }
    }
    #undef LOADF

    // epilogue: scale by pair weight, store float2
    #pragma unroll
    for (int mi = 0; mi < 4; ++mi) {
        int rl0 = wm + mi * 16 + grp;
        int rl1 = rl0 + 8;
        float w0 = s_w[rl0], w1 = s_w[rl1];
        #pragma unroll
        for (int ni = 0; ni < 8; ++ni) {
            int col = n0 + wn + ni * 8 + tg * 2;
            if (mb + rl0 < cnt) {
                float2 v = make_float2(c[mi][ni][0] * w0, c[mi][ni][1] * w0);
                *(float2*)&g_Yp[(size_t)(base + rl0) * H + col] = v;
            }
            if (mb + rl1 < cnt) {
                float2 v = make_float2(c[mi][ni][2] * w1, c[mi][ni][3] * w1);
                *(float2*)&g_Yp[(size_t)(base + rl1) * H + col] = v;
            }
        }
    }
}

// ---------------- combine: out[t] = EPS*sw + sum_k Yp[pos_k] ----------------
__global__ void combine_kernel(float* __restrict__ out, int T) {
    int t = blockIdx.x;
    int c4 = threadIdx.x;
    int b = t * TOPK;
    int p0 = g_pos[b + 0], p1 = g_pos[b + 1], p2 = g_pos[b + 2];
    int p3 = g_pos[b + 3], p4 = g_pos[b + 4], p5 = g_pos[b + 5];
    float bias = EPS * g_sw[t];
    int col = c4 * 4;

    float4 acc = make_float4(bias, bias, bias, bias);
    float4 y;
    y = *(const float4*)&g_Yp[(size_t)p0 * H + col]; acc.x += y.x; acc.y += y.y; acc.z += y.z; acc.w += y.w;
    y = *(const float4*)&g_Yp[(size_t)p1 * H + col]; acc.x += y.x; acc.y += y.y; acc.z += y.z; acc.w += y.w;
    y = *(const float4*)&g_Yp[(size_t)p2 * H + col]; acc.x += y.x; acc.y += y.y; acc.z += y.z; acc.w += y.w;
    y = *(const float4*)&g_Yp[(size_t)p3 * H + col]; acc.x += y.x; acc.y += y.y; acc.z += y.z; acc.w += y.w;
    y = *(const float4*)&g_Yp[(size_t)p4 * H + col]; acc.x += y.x; acc.y += y.y; acc.z += y.z; acc.w += y.w;
    y = *(const float4*)&g_Yp[(size_t)p5 * H + col]; acc.x += y.x; acc.y += y.y; acc.z += y.z; acc.w += y.w;

    *(float4*)&out[(size_t)t * H + col] = acc;
}

// ---------------- launch ----------------
extern "C" void kernel_launch(void* const* d_in, const int* in_sizes, int n_in,
                              void* d_out, int out_size) {
    const float* tokens = (const float*)d_in[0];
    const float* rw     = (const float*)d_in[1];
    const float* rb     = (const float*)d_in[2];
    const float* ew     = (const float*)d_in[3];
    float* out = (float*)d_out;

    int T = in_sizes[0] / H;   // 8192

    reset_kernel<<<1, 32>>>();                                        // idx 0

    cvt_w_kernel<<<(NEXP * H * H / 4 + 255) / 256, 256>>>(ew, NEXP * H * H / 4);  // idx 1

    cudaFuncSetAttribute(router_kernel,
                         cudaFuncAttributeMaxDynamicSharedMemorySize, NEXP * H * 4);
    int warps_per_blk = 8;   // 16 tokens per block
    int rblocks = (T / 2 + warps_per_blk - 1) / warps_per_blk;
    router_kernel<<<rblocks, warps_per_blk * 32, NEXP * H * 4>>>(tokens, rw, rb, T);  // idx 2

    cudaFuncSetAttribute(gemm_kernel,
                         cudaFuncAttributeMaxDynamicSharedMemorySize, SM_TOTAL);
    dim3 ggrid(H / BN, SEG / BM, NEXP);   // (8, 64, 16)
    gemm_kernel<<<ggrid, 128, SM_TOTAL>>>();                          // idx 3 <- profiled

    combine_kernel<<<T, 256>>>(out, T);                               // idx 4
}

// round 10
// speedup vs baseline: 2.3369x; 1.6341x over previous
#include <cuda_runtime.h>
#include <cuda_fp16.h>
#include <math.h>
#include <cstdint>

#define H 1024
#define H2 512                 // H in half2 words
#define NEXP 16
#define TOPK 6
#define EPS 1e-10f
#define MAXT 8192
#define SEG 8192

// GEMM: CTA tile 128x128, K-tile = 64 halves (32 half2 words), fp16 m16n8k16 MMA,
// 128 threads (2x2 warps of 64x64), 3 smem stages, 2 CTAs/SM.
#define BM 128
#define BN 128
#define BKW 32                 // K-tile in half2 words (= 64 halves)
#define NKT (H2 / BKW)         // 16
#define STG 3
#define AST 36                 // A row stride words (32 data + 4 pad)
#define BSTRIDE 136            // B row stride words (128 data + 8 pad)
#define A_BYTES (BM * AST * 4)           // 18432
#define B_BYTES (BKW * BSTRIDE * 4)      // 17408
#define STAGE_BYTES (A_BYTES + B_BYTES)  // 35840
#define SM_TOK (STG * STAGE_BYTES)       // 107520
#define SM_W   (SM_TOK + 512)
#define SM_TOTAL (SM_W + 512)            // 108544 (x2 CTAs = 217KB)

// ---------------- device scratch ----------------
__device__ int     g_cursor[NEXP];
__device__ float   g_sw[MAXT];
__device__ int     g_pair_token[NEXP * SEG];
__device__ float   g_pairw[NEXP * SEG];
__device__ int     g_pos[MAXT * TOPK];
__device__ __half2 g_Yp[(size_t)NEXP * SEG * H2];   // 256MB expert outputs (fp16)
__device__ __half2 g_Wt[(size_t)NEXP * H2 * H];     // 128MB W packed [e][k/2][n]
__device__ __half2 g_Xt[(size_t)MAXT * H2];         // 16MB  X packed [t][k/2]

// ---------------- helpers ----------------
__device__ __forceinline__ uint32_t s2u(const void* p) {
    uint32_t a;
    asm("{ .reg .u64 t; cvta.to.shared.u64 t, %1; cvt.u32.u64 %0, t; }"
        : "=r"(a) : "l"(p));
    return a;
}
__device__ __forceinline__ void cpa16(uint32_t dst, const void* src) {
    asm volatile("cp.async.cg.shared.global [%0], [%1], 16;" :: "r"(dst), "l"(src));
}
__device__ __forceinline__ void cpa_commit() {
    asm volatile("cp.async.commit_group;" ::: "memory");
}
__device__ __forceinline__ void cpa_wait1() {
    asm volatile("cp.async.wait_group 1;" ::: "memory");
}
// fp16 MMA: D(f32) += A(f16) * B(f16); m16n8k16
__device__ __forceinline__ void mma16(float* c, const unsigned* a, const unsigned* b) {
    asm volatile(
        "mma.sync.aligned.m16n8k16.row.col.f32.f16.f16.f32 "
        "{%0,%1,%2,%3}, {%4,%5,%6,%7}, {%8,%9}, {%0,%1,%2,%3};"
        : "+f"(c[0]), "+f"(c[1]), "+f"(c[2]), "+f"(c[3])
        : "r"(a[0]), "r"(a[1]), "r"(a[2]), "r"(a[3]), "r"(b[0]), "r"(b[1]));
}

// ---------------- reset ----------------
__global__ void reset_kernel() {
    int i = threadIdx.x;
    if (i < NEXP) g_cursor[i] = 0;
}

// ---------------- pack W: g_Wt[e][k/2][n] = half2(W[e][k][n], W[e][k+1][n]) ----------------
__global__ void cvt_w_kernel(const float* __restrict__ src) {
    int idx = blockIdx.x * blockDim.x + threadIdx.x;   // over NEXP*H2*H words
    if (idx >= NEXP * H2 * H) return;
    int n = idx & (H - 1);
    int kpg = idx >> 10;             // e*H2 + kp
    int e = kpg >> 9;
    int kp = kpg & (H2 - 1);
    size_t so = ((size_t)e * H + 2 * kp) * H + n;
    g_Wt[idx] = __floats2half2_rn(src[so], src[so + H]);
}

// ---------------- router: 2 tokens per warp; packs X to fp16 and scatters ----------------
__global__ void router_kernel(const float* __restrict__ x,
                              const float* __restrict__ rw,
                              const float* __restrict__ rb, int T) {
    extern __shared__ float s_rw[];

    int tid = threadIdx.x;
    for (int i = tid; i < NEXP * H; i += blockDim.x) s_rw[i] = rw[i];
    __syncthreads();

    int warp = tid >> 5, lane = tid & 31;
    int t0 = (blockIdx.x * (blockDim.x >> 5) + warp) * 2;
    if (t0 >= T) return;

    const float2* xr0 = (const float2*)(x + (size_t)t0 * H);
    const float2* xr1 = (const float2*)(x + (size_t)(t0 + 1) * H);

    float acc0[NEXP], acc1[NEXP];
    #pragma unroll
    for (int e = 0; e < NEXP; ++e) { acc0[e] = 0.f; acc1[e] = 0.f; }
    for (int ii = lane; ii < H2; ii += 32) {
        float2 v0 = xr0[ii], v1 = xr1[ii];
        g_Xt[(size_t)t0 * H2 + ii]       = __floats2half2_rn(v0.x, v0.y);
        g_Xt[(size_t)(t0 + 1) * H2 + ii] = __floats2half2_rn(v1.x, v1.y);
        #pragma unroll
        for (int e = 0; e < NEXP; ++e) {
            float2 w = ((const float2*)(s_rw + e * H))[ii];
            acc0[e] += v0.x * w.x + v0.y * w.y;
            acc1[e] += v1.x * w.x + v1.y * w.y;
        }
    }

    #pragma unroll
    for (int tk = 0; tk < 2; ++tk) {
        int t = t0 + tk;
        float logit;
        {
            float a[NEXP];
            #pragma unroll
            for (int e = 0; e < NEXP; ++e) a[e] = tk ? acc1[e] : acc0[e];
            #pragma unroll
            for (int e = 0; e < NEXP; ++e) {
                #pragma unroll
                for (int o = 16; o > 0; o >>= 1)
                    a[e] += __shfl_xor_sync(0xffffffffu, a[e], o);
            }
            logit = (lane < NEXP) ? (a[lane] + rb[lane]) : -INFINITY;
        }

        float mx = logit;
        #pragma unroll
        for (int o = 16; o > 0; o >>= 1)
            mx = fmaxf(mx, __shfl_xor_sync(0xffffffffu, mx, o));
        float p = (lane < NEXP) ? expf(logit - mx) : 0.f;
        float sum = p;
        #pragma unroll
        for (int o = 16; o > 0; o >>= 1)
            sum += __shfl_xor_sync(0xffffffffu, sum, o);
        float prob = p / sum;

        float cur = (lane < NEXP) ? prob : -1.f;
        float tv[TOPK]; int ti[TOPK];
        float s = 0.f;
        #pragma unroll
        for (int k = 0; k < TOPK; ++k) {
            float v = cur; int bi = lane;
            #pragma unroll
            for (int o = 16; o > 0; o >>= 1) {
                float ov = __shfl_xor_sync(0xffffffffu, v, o);
                int   oi = __shfl_xor_sync(0xffffffffu, bi, o);
                if (ov > v || (ov == v && oi < bi)) { v = ov; bi = oi; }
            }
            tv[k] = v; ti[k] = bi;
            s += v;
            if (lane == bi) cur = -1.f;
        }
        if (lane == 0) {
            float inv = 1.f / (s + EPS);
            float w[TOPK], sw = 0.f;
            #pragma unroll
            for (int k = 0; k < TOPK; ++k) { w[k] = tv[k] * inv; sw += w[k]; }
            g_sw[t] = sw;
            float isw = 1.f / sw;
            int b = t * TOPK;
            #pragma unroll
            for (int k = 0; k < TOPK; ++k) {
                int e = ti[k];
                int pos = atomicAdd(&g_cursor[e], 1);
                int row = e * SEG + pos;
                g_pair_token[row] = t;
                g_pairw[row] = w[k] * isw;
                g_pos[b + k] = row;
            }
        }
    }
}

// ---------------- grouped GEMM: fp16 m16n8k16, 128x128 tile, 3-stage, 2 CTAs/SM ----------------
__global__ void __launch_bounds__(128, 2) gemm_kernel() {
    extern __shared__ char smem[];
    const int e   = blockIdx.z;
    const int cnt = g_cursor[e];
    const int mb  = blockIdx.y * BM;
    if (mb >= cnt) return;
    const int base = e * SEG + mb;
    const int n0 = blockIdx.x * BN;

    const uint32_t sb = s2u(smem);
    const int tid = threadIdx.x;
    int*   s_tok = (int*)(smem + SM_TOK);
    float* s_w   = (float*)(smem + SM_W);

    if (tid < BM) {
        bool ok = (mb + tid) < cnt;
        s_tok[tid] = ok ? g_pair_token[base + tid] : 0;
        s_w[tid]   = ok ? g_pairw[base + tid] : 0.f;
    }
    __syncthreads();

    const __half2* wb = g_Wt + (size_t)e * H2 * H + n0;

    // per stage: A 128 rows x 32 words (8 cp16/thread), B 32 kp-rows x 128 words (8 cp16/thread)
    auto issue = [&](int s, int kt) {
        const int k0 = kt * BKW;
        uint32_t ab = sb + s * STAGE_BYTES;
        #pragma unroll
        for (int p = 0; p < 8; ++p) {
            int idx = tid + p * 128;
            int row = idx >> 3, i = idx & 7;
            cpa16(ab + (row * AST + i * 4) * 4,
                  g_Xt + (size_t)s_tok[row] * H2 + k0 + i * 4);
        }
        uint32_t bb = ab + A_BYTES;
        #pragma unroll
        for (int p = 0; p < 8; ++p) {
            int idx = tid + p * 128;
            int kr = idx >> 5, i = idx & 31;
            cpa16(bb + (kr * BSTRIDE + i * 4) * 4,
                  wb + (size_t)(k0 + kr) * H + i * 4);
        }
    };

    issue(0, 0); cpa_commit();
    issue(1, 1); cpa_commit();

    float c[4][8][4];
    #pragma unroll
    for (int mi = 0; mi < 4; ++mi)
        #pragma unroll
        for (int ni = 0; ni < 8; ++ni)
            #pragma unroll
            for (int j = 0; j < 4; ++j) c[mi][ni][j] = 0.f;

    const int lane = tid & 31;
    const int grp = lane >> 2, tg = lane & 3;
    const int wid = tid >> 5;
    const int wm = (wid >> 1) * 64;
    const int wn = (wid & 1) * 64;

    unsigned a[2][4][4], b[2][8][2];

    // fragment loads: word index = k/2; a0={r, 2tg..}, a1={r+8}, a2={r, +8 halves}, a3={r+8,+8}
    #define LOADF(buf, kk)                                                   \
        { const int k8 = (kk) * 8;                                           \
          _Pragma("unroll")                                                  \
          for (int mi = 0; mi < 4; ++mi) {                                   \
            int r = wm + mi * 16 + grp;                                      \
            a[buf][mi][0] = As[r * AST + k8 + tg];                           \
            a[buf][mi][1] = As[(r + 8) * AST + k8 + tg];                     \
            a[buf][mi][2] = As[r * AST + k8 + tg + 4];                       \
            a[buf][mi][3] = As[(r + 8) * AST + k8 + tg + 4];                 \
          }                                                                  \
          _Pragma("unroll")                                                  \
          for (int ni = 0; ni < 8; ++ni) {                                   \
            int cn = wn + ni * 8 + grp;                                      \
            b[buf][ni][0] = Bs[(k8 + tg) * BSTRIDE + cn];                    \
            b[buf][ni][1] = Bs[(k8 + tg + 4) * BSTRIDE + cn];                \
          } }

    for (int kt = 0; kt < NKT; ++kt) {
        cpa_wait1();
        __syncthreads();
        if (kt + 2 < NKT) issue((kt + 2) % STG, kt + 2);
        cpa_commit();

        const unsigned* As = (const unsigned*)(smem + (kt % STG) * STAGE_BYTES);
        const unsigned* Bs = As + BM * AST;

        LOADF(0, 0);
        #pragma unroll
        for (int kk = 0; kk < 4; ++kk) {
            const int cur = kk & 1;
            if (kk < 3) LOADF(cur ^ 1, kk + 1);
            #pragma unroll
            for (int mi = 0; mi < 4; ++mi)
                #pragma unroll
                for (int ni = 0; ni < 8; ++ni)
                    mma16(c[mi][ni], a[cur][mi], b[cur][ni]);
        }
    }
    #undef LOADF

    // epilogue: scale by pair weight, store half2
    #pragma unroll
    for (int mi = 0; mi < 4; ++mi) {
        int rl0 = wm + mi * 16 + grp;
        int rl1 = rl0 + 8;
        float w0 = s_w[rl0], w1 = s_w[rl1];
        #pragma unroll
        for (int ni = 0; ni < 8; ++ni) {
            int colw = (n0 + wn + ni * 8 + tg * 2) >> 1;
            if (mb + rl0 < cnt)
                g_Yp[(size_t)(base + rl0) * H2 + colw] =
                    __floats2half2_rn(c[mi][ni][0] * w0, c[mi][ni][1] * w0);
            if (mb + rl1 < cnt)
                g_Yp[(size_t)(base + rl1) * H2 + colw] =
                    __floats2half2_rn(c[mi][ni][2] * w1, c[mi][ni][3] * w1);
        }
    }
}

// ---------------- combine: out[t] = EPS*sw + sum_k Yp[pos_k] ----------------
__global__ void combine_kernel(float* __restrict__ out, int T) {
    int t = blockIdx.x;
    int c4 = threadIdx.x;             // 256 threads x 4 cols
    int b = t * TOPK;
    float bias = EPS * g_sw[t];
    int cw = c4 * 2;                  // half2 word index (2 words = 4 cols)

    float4 acc = make_float4(bias, bias, bias, bias);
    #pragma unroll
    for (int k = 0; k < TOPK; ++k) {
        int p = g_pos[b + k];
        uint2 u = *(const uint2*)(g_Yp + (size_t)p * H2 + cw);
        float2 lo = __half22float2(*(__half2*)&u.x);
        float2 hi = __half22float2(*(__half2*)&u.y);
        acc.x += lo.x; acc.y += lo.y; acc.z += hi.x; acc.w += hi.y;
    }
    *(float4*)&out[(size_t)t * H + c4 * 4] = acc;
}

// ---------------- launch ----------------
extern "C" void kernel_launch(void* const* d_in, const int* in_sizes, int n_in,
                              void* d_out, int out_size) {
    const float* tokens = (const float*)d_in[0];
    const float* rw     = (const float*)d_in[1];
    const float* rb     = (const float*)d_in[2];
    const float* ew     = (const float*)d_in[3];
    float* out = (float*)d_out;

    int T = in_sizes[0] / H;   // 8192

    reset_kernel<<<1, 32>>>();                                        // idx 0

    cvt_w_kernel<<<(NEXP * H2 * H + 255) / 256, 256>>>(ew);           // idx 1

    cudaFuncSetAttribute(router_kernel,
                         cudaFuncAttributeMaxDynamicSharedMemorySize, NEXP * H * 4);
    int warps_per_blk = 8;   // 16 tokens per block
    int rblocks = (T / 2 + warps_per_blk - 1) / warps_per_blk;
    router_kernel<<<rblocks, warps_per_blk * 32, NEXP * H * 4>>>(tokens, rw, rb, T);  // idx 2

    cudaFuncSetAttribute(gemm_kernel,
                         cudaFuncAttributeMaxDynamicSharedMemorySize, SM_TOTAL);
    dim3 ggrid(H / BN, SEG / BM, NEXP);   // (8, 64, 16)
    gemm_kernel<<<ggrid, 128, SM_TOTAL>>>();                          // idx 3 <- profiled

    combine_kernel<<<T, 256>>>(out, T);                               // idx 4
}